// round 11
// baseline (speedup 1.0000x reference)
#include <cuda_runtime.h>
#include <cuda_fp16.h>
#include <math.h>
#include <stdint.h>

#define Bsz 256
#define Hd  512
#define Ld  2
#define Td  64
#define Od  7
#define G4  2048
#define Kd  1024
#define BH  (Bsz*Hd)

#define LOSCALE 2048.0f
#define LOINV   (1.0f/2048.0f)

// ---- device scratch (allocation forbidden) ----
__device__ __half g_Whi[Ld*G4*Kd];
__device__ __half g_Wlo[Ld*G4*Kd];
__device__ float  g_bias[Ld*G4];
__device__ float  g_h[Ld*BH];
__device__ float  g_c[Ld*BH];
__device__ __half g_bhi[Ld*2*BH];   // [layer][parity][B][H]
__device__ __half g_blo[Ld*2*BH];
__device__ __half g_xhi[BH];
__device__ __half g_xlo[BH];

__device__ __forceinline__ unsigned smaddr(const void* p) {
    return (unsigned)__cvta_generic_to_shared(p);
}
__device__ __forceinline__ void cp16(unsigned s, const void* g) {
    asm volatile("cp.async.cg.shared.global [%0], [%1], 16;\n" :: "r"(s), "l"(g));
}
__device__ __forceinline__ void ldsm4(unsigned* r, unsigned addr) {
    asm volatile("ldmatrix.sync.aligned.m8n8.x4.shared.b16 {%0,%1,%2,%3}, [%4];\n"
        : "=r"(r[0]), "=r"(r[1]), "=r"(r[2]), "=r"(r[3]) : "r"(addr));
}
__device__ __forceinline__ void mma16816(float* c, const unsigned* a, const unsigned* b) {
    asm volatile("mma.sync.aligned.m16n8k16.row.col.f32.f16.f16.f32 "
        "{%0,%1,%2,%3}, {%4,%5,%6,%7}, {%8,%9}, {%0,%1,%2,%3};\n"
        : "+f"(c[0]), "+f"(c[1]), "+f"(c[2]), "+f"(c[3])
        : "r"(a[0]), "r"(a[1]), "r"(a[2]), "r"(a[3]), "r"(b[0]), "r"(b[1]));
}
__device__ __forceinline__ float sigf(float x) { return 1.0f / (1.0f + expf(-x)); }

// ---- prep: gate-interleaved combined weights + hi/lo split + bias fold ----
__global__ void prep_weights(const float* __restrict__ Wih, const float* __restrict__ Whh,
                             const float* __restrict__ bih, const float* __restrict__ bhh) {
    int idx = blockIdx.x * 256 + threadIdx.x;
    if (idx >= Ld*G4*Kd) return;
    int k = idx & (Kd - 1);
    int n = (idx >> 10) & (G4 - 1);
    int l = idx >> 21;
    int u = n >> 2, gi = n & 3;
    int srow = gi * Hd + u;
    float w = (k < Hd) ? Wih[((size_t)l*G4 + srow)*Hd + k]
                       : Whh[((size_t)l*G4 + srow)*Hd + (k - Hd)];
    __half hi = __float2half_rn(w);
    g_Whi[idx] = hi;
    g_Wlo[idx] = __float2half_rn((w - __half2float(hi)) * LOSCALE);
    if (k == 0) g_bias[l*G4 + n] = bih[l*G4 + srow] + bhh[l*G4 + srow];
}

__global__ void prep_state(const float* __restrict__ x, const float* __restrict__ h0,
                           const float* __restrict__ c0) {
    int idx = blockIdx.x * 256 + threadIdx.x;
    if (idx >= Ld*BH) return;
    float h = h0[idx];
    g_h[idx] = h;
    g_c[idx] = c0[idx];
    int l = idx / BH, ru = idx - l*BH;
    __half hi = __float2half_rn(h);
    int bi = (l*2 + 1)*BH + ru;           // parity 1 = "previous" for t=0
    g_bhi[bi] = hi;
    g_blo[bi] = __float2half_rn((h - __half2float(hi)) * LOSCALE);
    if (idx < BH) {
        float xv = x[idx];
        __half xh = __float2half_rn(xv);
        g_xhi[idx] = xh;
        g_xlo[idx] = __float2half_rn((xv - __half2float(xh)) * LOSCALE);
    }
}

// ---- fused GEMM + LSTM cell: 16 warps (4x4, 16x16/warp), 3-stage pipeline ----
#define STRD  72                 // halves per smem row (64 data + 8 pad)
#define ARRH  (64*STRD)          // halves per operand array (4608)
#define STGH  (4*ARRH)           // halves per stage (18432) = 36864 B
#define NSTG  3
#define DSMEM (NSTG*STGH*2)      // 110592 bytes

__global__ __launch_bounds__(512, 1)
void lstm_layer(int l, int t, const float* __restrict__ Wfc,
                const float* __restrict__ bfc, float* __restrict__ out)
{
    const int p = t & 1, pp = p ^ 1;
    const int bx = blockIdx.x;
    const int tid = threadIdx.x;

    // spare CTAs (layer-0 grid only): y_{t-1} = h1 @ Wfc^T + bfc
    if (bx >= 128) {
        if (t == 0) return;
        int yb = bx - 128;
        for (int pr = tid; pr < 32*Od; pr += 512) {
            int rl = pr / Od, o = pr - rl*Od;
            int R = yb*32 + rl;
            const float4* h4 = (const float4*)(g_h + BH + (size_t)R*Hd);
            const float4* w4 = (const float4*)(Wfc + (size_t)o*Hd);
            float acc = 0.f;
            #pragma unroll 16
            for (int j = 0; j < Hd/4; j++) {
                float4 a = h4[j], b = w4[j];
                acc += a.x*b.x + a.y*b.y + a.z*b.z + a.w*b.w;
            }
            out[(size_t)R*(Td*Od) + (t-1)*Od + o] = acc + bfc[o];
        }
        return;
    }

    const __half *inpHi, *inpLo, *ownHi, *ownLo;
    if (l == 0) {
        if (t == 0) { inpHi = g_xhi; inpLo = g_xlo; }
        else { inpHi = g_bhi + (2 + pp)*BH; inpLo = g_blo + (2 + pp)*BH; }
        ownHi = g_bhi + pp*BH;            ownLo = g_blo + pp*BH;
    } else {
        inpHi = g_bhi + p*BH;             inpLo = g_blo + p*BH;
        ownHi = g_bhi + (2 + pp)*BH;      ownLo = g_blo + (2 + pp)*BH;
    }

    const int mTile = bx & 3, nTile = bx >> 2;
    const int bm0 = mTile * 64, bn0 = nTile * 64;

    extern __shared__ __align__(16) __half dynsm[];
    __shared__ float sBias[64];
    if (tid < 64) sBias[tid] = g_bias[l*G4 + bn0 + tid];

    const __half* wHiBase = g_Whi + ((size_t)l*G4 + bn0) * Kd;
    const __half* wLoBase = g_Wlo + ((size_t)l*G4 + bn0) * Kd;

    const int lane = tid & 31, warp = tid >> 5;
    const int wm = warp & 3, wn = warp >> 2;       // 4 x 4 warps, 16x16 each
    const int m0w = wm*16, n0w = wn*16;
    const int gid = lane >> 2, tid4 = lane & 3;

    // LDSM per-thread invariant byte addresses
    const unsigned smB = smaddr(dynsm);
    // A: lanes 0-15 -> rows m0w..m0w+15, lanes 16-31 -> same rows at k+8
    const unsigned aBase = smB + 2u*((unsigned)(m0w + (lane & 15))*STRD + ((lane >> 4) << 3));
    // B: 4 groups of 8 lanes -> (ni_local = g>>1, khalf = g&1), rows n
    const int g2 = lane >> 3;
    const unsigned bBase = smB + 2u*((unsigned)(2*ARRH) +
                           (unsigned)(n0w + (g2 >> 1)*8 + (lane & 7))*STRD + (unsigned)((g2 & 1) << 3));

    float accH[2][4] = {};
    float accL[2][4] = {};

    auto load_chunk = [&](int c, int stage) {
        int k0 = c * 64;
        const __half *ah, *al; int kl;
        if (k0 < Hd) { ah = inpHi; al = inpLo; kl = k0; }
        else         { ah = ownHi; al = ownLo; kl = k0 - Hd; }
        __half* st = dynsm + stage * STGH;
        {
            int gq = tid;                    // 512 quads per array
            int row = gq >> 3, qc = gq & 7;  // 64 rows x 8 x 16B
            unsigned so = (unsigned)(row*STRD + qc*8);
            cp16(smaddr(st + so),          ah + (size_t)(bm0 + row)*Hd + kl + qc*8);
            cp16(smaddr(st + ARRH + so),   al + (size_t)(bm0 + row)*Hd + kl + qc*8);
            cp16(smaddr(st + 2*ARRH + so), wHiBase + (size_t)row*Kd + k0 + qc*8);
            cp16(smaddr(st + 3*ARRH + so), wLoBase + (size_t)row*Kd + k0 + qc*8);
        }
        asm volatile("cp.async.commit_group;\n");
    };

    load_chunk(0, 0);
    load_chunk(1, 1);

    int stage = 0;
    #pragma unroll 1
    for (int c = 0; c < 16; c++) {
        if (c < 15) asm volatile("cp.async.wait_group 1;\n");
        else        asm volatile("cp.async.wait_group 0;\n");
        __syncthreads();
        if (c + 2 < 16) load_chunk(c + 2, (stage + 2) % NSTG);

        const unsigned so = (unsigned)(stage * (2*STGH));   // byte stage offset

        #pragma unroll
        for (int kk = 0; kk < 64; kk += 16) {
            unsigned aH[4], aL[4], bH[4], bL[4];
            {
                unsigned ad = aBase + so + 2u*(unsigned)kk;
                ldsm4(aH, ad);
                ldsm4(aL, ad + 2u*ARRH);
            }
            {
                unsigned bd = bBase + so + 2u*(unsigned)kk;
                ldsm4(bH, bd);
                ldsm4(bL, bd + 2u*ARRH);
            }
            #pragma unroll
            for (int ni = 0; ni < 2; ni++)
                mma16816(accH[ni], aH, &bH[2*ni]);   // Ahi*Whi
            #pragma unroll
            for (int ni = 0; ni < 2; ni++)
                mma16816(accL[ni], aL, &bH[2*ni]);   // 2^11*Alo*Whi
            #pragma unroll
            for (int ni = 0; ni < 2; ni++)
                mma16816(accL[ni], aH, &bL[2*ni]);   // 2^11*Ahi*Wlo
        }
        stage = (stage + 1) % NSTG;
    }
    __syncthreads();

    // epilogue: reuse smem as fp32 gate tile (64 x 64, stride 66)
    float* sG = reinterpret_cast<float*>(dynsm);
    #pragma unroll
    for (int ni = 0; ni < 2; ni++) {
        int r0 = m0w + gid;
        int c0 = n0w + ni*8 + 2*tid4;
        sG[r0*66 + c0]       = accH[ni][0] + accL[ni][0]*LOINV;
        sG[r0*66 + c0 + 1]   = accH[ni][1] + accL[ni][1]*LOINV;
        sG[(r0+8)*66 + c0]   = accH[ni][2] + accL[ni][2]*LOINV;
        sG[(r0+8)*66 + c0+1] = accH[ni][3] + accL[ni][3]*LOINV;
    }
    __syncthreads();

    const int Ubase = bn0 >> 2;
    #pragma unroll
    for (int s = 0; s < 2; s++) {
        int pi = tid + 512*s;               // 1024 (row,unit) pairs
        int r = pi >> 4, u = pi & 15;
        float gi = sigf(  sG[r*66 + 4*u + 0] + sBias[4*u + 0]);
        float gf = sigf(  sG[r*66 + 4*u + 1] + sBias[4*u + 1]);
        float gg = tanhf( sG[r*66 + 4*u + 2] + sBias[4*u + 2]);
        float go = sigf(  sG[r*66 + 4*u + 3] + sBias[4*u + 3]);
        size_t ci = (size_t)l*BH + (size_t)(bm0 + r)*Hd + Ubase + u;
        float cnew = gf * g_c[ci] + gi * gg;
        float hnew = go * tanhf(cnew);
        g_c[ci] = cnew;
        g_h[ci] = hnew;
        __half hi = __float2half_rn(hnew);
        size_t bi = (size_t)(l*2 + p)*BH + (size_t)(bm0 + r)*Hd + Ubase + u;
        g_bhi[bi] = hi;
        g_blo[bi] = __float2half_rn((hnew - __half2float(hi)) * LOSCALE);
    }
}

// ---- finalize: y_63 + hT/cT ----
__global__ void finalize(const float* __restrict__ Wfc, const float* __restrict__ bfc,
                         float* __restrict__ out) {
    const int N1 = Ld*BH / 2;
    int idx = blockIdx.x * 256 + threadIdx.x;
    if (idx < 2*N1) {
        out[(size_t)Bsz*Td*Od + idx] = g_h[idx];           // hT
        out[(size_t)Bsz*Td*Od + 2*N1 + idx] = g_c[idx];    // cT
        return;
    }
    int idx2 = idx - 2*N1;
    if (idx2 >= Bsz*Od) return;
    int r = idx2 / Od, o = idx2 - r*Od;
    const float4* h4 = (const float4*)(g_h + BH + (size_t)r*Hd);
    const float4* w4 = (const float4*)(Wfc + (size_t)o*Hd);
    float acc = 0.f;
    #pragma unroll 16
    for (int j = 0; j < Hd/4; j++) {
        float4 a = h4[j], b = w4[j];
        acc += a.x*b.x + a.y*b.y + a.z*b.z + a.w*b.w;
    }
    out[(size_t)r*(Td*Od) + (Td-1)*Od + o] = acc + bfc[o];
}

extern "C" void kernel_launch(void* const* d_in, const int* in_sizes, int n_in,
                              void* d_out, int out_size) {
    const float* x   = (const float*)d_in[0];
    const float* h0  = (const float*)d_in[1];
    const float* c0  = (const float*)d_in[2];
    const float* Wih = (const float*)d_in[3];
    const float* Whh = (const float*)d_in[4];
    const float* bih = (const float*)d_in[5];
    const float* bhh = (const float*)d_in[6];
    const float* Wfc = (const float*)d_in[7];
    const float* bfc = (const float*)d_in[8];
    float* out = (float*)d_out;

    static int smem_set = 0;
    if (!smem_set) {
        cudaFuncSetAttribute(lstm_layer, cudaFuncAttributeMaxDynamicSharedMemorySize, DSMEM);
        smem_set = 1;
    }

    prep_weights<<<(Ld*G4*Kd + 255)/256, 256>>>(Wih, Whh, bih, bhh);
    prep_state<<<(Ld*BH + 255)/256, 256>>>(x, h0, c0);

    for (int t = 0; t < Td; t++) {
        lstm_layer<<<136, 512, DSMEM>>>(0, t, Wfc, bfc, out);   // + y_{t-1} in spare CTAs
        lstm_layer<<<128, 512, DSMEM>>>(1, t, Wfc, bfc, out);
    }
    finalize<<<(Ld*BH + Bsz*Od + 255)/256, 256>>>(Wfc, bfc, out);
}

// round 12
// speedup vs baseline: 1.1112x; 1.1112x over previous
#include <cuda_runtime.h>
#include <cuda_fp16.h>
#include <math.h>
#include <stdint.h>

#define Bsz 256
#define Hd  512
#define Ld  2
#define Td  64
#define Od  7
#define G4  2048
#define Kd  1024
#define BH  (Bsz*Hd)

#define LOSCALE 2048.0f
#define LOINV   (1.0f/2048.0f)

// ---- device scratch (allocation forbidden) ----
__device__ __half g_Whi[Ld*G4*Kd];
__device__ float  g_bias[Ld*G4];
__device__ float  g_h[Ld*BH];
__device__ float  g_c[Ld*BH];
__device__ __half g_bhi[Ld*2*BH];   // [layer][parity][B][H]
__device__ __half g_blo[Ld*2*BH];
__device__ __half g_xhi[BH];
__device__ __half g_xlo[BH];

__device__ __forceinline__ unsigned smaddr(const void* p) {
    return (unsigned)__cvta_generic_to_shared(p);
}
__device__ __forceinline__ void cp16(unsigned s, const void* g) {
    asm volatile("cp.async.cg.shared.global [%0], [%1], 16;\n" :: "r"(s), "l"(g));
}
__device__ __forceinline__ void ldsm4(unsigned* r, unsigned addr) {
    asm volatile("ldmatrix.sync.aligned.m8n8.x4.shared.b16 {%0,%1,%2,%3}, [%4];\n"
        : "=r"(r[0]), "=r"(r[1]), "=r"(r[2]), "=r"(r[3]) : "r"(addr));
}
__device__ __forceinline__ void mma16816(float* c, const unsigned* a, const unsigned* b) {
    asm volatile("mma.sync.aligned.m16n8k16.row.col.f32.f16.f16.f32 "
        "{%0,%1,%2,%3}, {%4,%5,%6,%7}, {%8,%9}, {%0,%1,%2,%3};\n"
        : "+f"(c[0]), "+f"(c[1]), "+f"(c[2]), "+f"(c[3])
        : "r"(a[0]), "r"(a[1]), "r"(a[2]), "r"(a[3]), "r"(b[0]), "r"(b[1]));
}
__device__ __forceinline__ float sigf(float x) { return 1.0f / (1.0f + expf(-x)); }

// ---- prep: gate-interleaved combined weights (fp16 hi only) + bias fold ----
__global__ void prep_weights(const float* __restrict__ Wih, const float* __restrict__ Whh,
                             const float* __restrict__ bih, const float* __restrict__ bhh) {
    int idx = blockIdx.x * 256 + threadIdx.x;
    if (idx >= Ld*G4*Kd) return;
    int k = idx & (Kd - 1);
    int n = (idx >> 10) & (G4 - 1);
    int l = idx >> 21;
    int u = n >> 2, gi = n & 3;
    int srow = gi * Hd + u;
    float w = (k < Hd) ? Wih[((size_t)l*G4 + srow)*Hd + k]
                       : Whh[((size_t)l*G4 + srow)*Hd + (k - Hd)];
    g_Whi[idx] = __float2half_rn(w);
    if (k == 0) g_bias[l*G4 + n] = bih[l*G4 + srow] + bhh[l*G4 + srow];
}

__global__ void prep_state(const float* __restrict__ x, const float* __restrict__ h0,
                           const float* __restrict__ c0) {
    int idx = blockIdx.x * 256 + threadIdx.x;
    if (idx >= Ld*BH) return;
    float h = h0[idx];
    g_h[idx] = h;
    g_c[idx] = c0[idx];
    int l = idx / BH, ru = idx - l*BH;
    __half hi = __float2half_rn(h);
    int bi = (l*2 + 1)*BH + ru;           // parity 1 = "previous" for t=0
    g_bhi[bi] = hi;
    g_blo[bi] = __float2half_rn((h - __half2float(hi)) * LOSCALE);
    if (idx < BH) {
        float xv = x[idx];
        __half xh = __float2half_rn(xv);
        g_xhi[idx] = xh;
        g_xlo[idx] = __float2half_rn((xv - __half2float(xh)) * LOSCALE);
    }
}

// ---- fused GEMM + LSTM cell: 8 warps (2x4, 32x16/warp), 2 MMA products ----
#define STRD  72                 // halves per smem row (64 data + 8 pad)
#define ARRH  (64*STRD)          // halves per operand array (4608)
#define STGH  (3*ARRH)           // halves per stage: [Ahi, Alo, Whi] = 27648 B
#define NSTG  3
#define DSMEM (NSTG*STGH*2)      // 82944 bytes

__global__ __launch_bounds__(256, 1)
void lstm_layer(int l, int t, const float* __restrict__ Wfc,
                const float* __restrict__ bfc, float* __restrict__ out)
{
    const int p = t & 1, pp = p ^ 1;
    const int bx = blockIdx.x;
    const int tid = threadIdx.x;

    // spare CTAs (layer-0 grid only): y_{t-1} = h1 @ Wfc^T + bfc
    if (bx >= 128) {
        if (t == 0) return;
        int yb = bx - 128;
        for (int pr = tid; pr < 32*Od; pr += 256) {
            int rl = pr / Od, o = pr - rl*Od;
            int R = yb*32 + rl;
            const float4* h4 = (const float4*)(g_h + BH + (size_t)R*Hd);
            const float4* w4 = (const float4*)(Wfc + (size_t)o*Hd);
            float acc = 0.f;
            #pragma unroll 16
            for (int j = 0; j < Hd/4; j++) {
                float4 a = h4[j], b = w4[j];
                acc += a.x*b.x + a.y*b.y + a.z*b.z + a.w*b.w;
            }
            out[(size_t)R*(Td*Od) + (t-1)*Od + o] = acc + bfc[o];
        }
        return;
    }

    const __half *inpHi, *inpLo, *ownHi, *ownLo;
    if (l == 0) {
        if (t == 0) { inpHi = g_xhi; inpLo = g_xlo; }
        else { inpHi = g_bhi + (2 + pp)*BH; inpLo = g_blo + (2 + pp)*BH; }
        ownHi = g_bhi + pp*BH;            ownLo = g_blo + pp*BH;
    } else {
        inpHi = g_bhi + p*BH;             inpLo = g_blo + p*BH;
        ownHi = g_bhi + (2 + pp)*BH;      ownLo = g_blo + (2 + pp)*BH;
    }

    const int mTile = bx & 3, nTile = bx >> 2;
    const int bm0 = mTile * 64, bn0 = nTile * 64;

    extern __shared__ __align__(16) __half dynsm[];
    __shared__ float sBias[64];
    if (tid < 64) sBias[tid] = g_bias[l*G4 + bn0 + tid];

    const __half* wHiBase = g_Whi + ((size_t)l*G4 + bn0) * Kd;

    const int lane = tid & 31, warp = tid >> 5;
    const int wm = warp & 1, wn = warp >> 1;       // 2 x 4 warps, 32x16 each
    const int m0w = wm*32, n0w = wn*16;
    const int gid = lane >> 2, tid4 = lane & 3;

    // LDSM per-thread invariant byte addresses
    const unsigned smB = smaddr(dynsm);
    const unsigned aBase = smB + 2u*((unsigned)(m0w + (lane & 15))*STRD + ((lane >> 4) << 3));
    const int g2 = lane >> 3;
    const unsigned bBase = smB + 2u*((unsigned)(2*ARRH) +
                           (unsigned)(n0w + (g2 >> 1)*8 + (lane & 7))*STRD + (unsigned)((g2 & 1) << 3));

    float accH[2][2][4] = {};
    float accL[2][2][4] = {};

    auto load_chunk = [&](int c, int stage) {
        int k0 = c * 64;
        const __half *ah, *al; int kl;
        if (k0 < Hd) { ah = inpHi; al = inpLo; kl = k0; }
        else         { ah = ownHi; al = ownLo; kl = k0 - Hd; }
        __half* st = dynsm + stage * STGH;
        #pragma unroll
        for (int j = 0; j < 6; j++) {
            int q = tid + 256*j;             // 1536 quads: 3 arrays x 512
            int arr = q >> 9, qq = q & 511;
            int row = qq >> 3, qc = qq & 7;  // 64 rows x 8 x 16B
            unsigned so = (unsigned)(arr*ARRH + row*STRD + qc*8);
            const __half* src;
            if (arr == 0)      src = ah + (size_t)(bm0 + row)*Hd + kl + qc*8;
            else if (arr == 1) src = al + (size_t)(bm0 + row)*Hd + kl + qc*8;
            else               src = wHiBase + (size_t)row*Kd + k0 + qc*8;
            cp16(smaddr(st + so), src);
        }
        asm volatile("cp.async.commit_group;\n");
    };

    load_chunk(0, 0);
    load_chunk(1, 1);

    int stage = 0;
    #pragma unroll 1
    for (int c = 0; c < 16; c++) {
        if (c < 15) asm volatile("cp.async.wait_group 1;\n");
        else        asm volatile("cp.async.wait_group 0;\n");
        __syncthreads();
        if (c + 2 < 16) load_chunk(c + 2, (stage + 2) % NSTG);

        const unsigned so = (unsigned)(stage * (2*STGH));   // byte stage offset

        #pragma unroll
        for (int kk = 0; kk < 64; kk += 16) {
            unsigned aH[2][4], aL[2][4], bH[4];
            #pragma unroll
            for (int mi = 0; mi < 2; mi++) {
                unsigned ad = aBase + so + 2u*(unsigned)(mi*16*STRD + kk);
                ldsm4(aH[mi], ad);
                ldsm4(aL[mi], ad + 2u*ARRH);
            }
            {
                unsigned bd = bBase + so + 2u*(unsigned)kk;
                ldsm4(bH, bd);
            }
            #pragma unroll
            for (int mi = 0; mi < 2; mi++)
                #pragma unroll
                for (int ni = 0; ni < 2; ni++)
                    mma16816(accH[mi][ni], aH[mi], &bH[2*ni]);   // Ahi*Whi
            #pragma unroll
            for (int mi = 0; mi < 2; mi++)
                #pragma unroll
                for (int ni = 0; ni < 2; ni++)
                    mma16816(accL[mi][ni], aL[mi], &bH[2*ni]);   // 2^11*Alo*Whi
        }
        stage = (stage + 1) % NSTG;
    }
    __syncthreads();

    // epilogue: reuse smem as fp32 gate tile (64 x 64, stride 66)
    float* sG = reinterpret_cast<float*>(dynsm);
    #pragma unroll
    for (int mi = 0; mi < 2; mi++)
        #pragma unroll
        for (int ni = 0; ni < 2; ni++) {
            int r0 = m0w + mi*16 + gid;
            int c0 = n0w + ni*8 + 2*tid4;
            sG[r0*66 + c0]       = accH[mi][ni][0] + accL[mi][ni][0]*LOINV;
            sG[r0*66 + c0 + 1]   = accH[mi][ni][1] + accL[mi][ni][1]*LOINV;
            sG[(r0+8)*66 + c0]   = accH[mi][ni][2] + accL[mi][ni][2]*LOINV;
            sG[(r0+8)*66 + c0+1] = accH[mi][ni][3] + accL[mi][ni][3]*LOINV;
        }
    __syncthreads();

    const int Ubase = bn0 >> 2;
    #pragma unroll
    for (int s = 0; s < 4; s++) {
        int pi = tid + 256*s;               // 1024 (row,unit) pairs
        int r = pi >> 4, u = pi & 15;
        float gi = sigf(  sG[r*66 + 4*u + 0] + sBias[4*u + 0]);
        float gf = sigf(  sG[r*66 + 4*u + 1] + sBias[4*u + 1]);
        float gg = tanhf( sG[r*66 + 4*u + 2] + sBias[4*u + 2]);
        float go = sigf(  sG[r*66 + 4*u + 3] + sBias[4*u + 3]);
        size_t ci = (size_t)l*BH + (size_t)(bm0 + r)*Hd + Ubase + u;
        float cnew = gf * g_c[ci] + gi * gg;
        float hnew = go * tanhf(cnew);
        g_c[ci] = cnew;
        g_h[ci] = hnew;
        __half hi = __float2half_rn(hnew);
        size_t bi = (size_t)(l*2 + p)*BH + (size_t)(bm0 + r)*Hd + Ubase + u;
        g_bhi[bi] = hi;
        g_blo[bi] = __float2half_rn((hnew - __half2float(hi)) * LOSCALE);
    }
}

// ---- finalize: y_63 + hT/cT ----
__global__ void finalize(const float* __restrict__ Wfc, const float* __restrict__ bfc,
                         float* __restrict__ out) {
    const int N1 = Ld*BH / 2;
    int idx = blockIdx.x * 256 + threadIdx.x;
    if (idx < 2*N1) {
        out[(size_t)Bsz*Td*Od + idx] = g_h[idx];           // hT
        out[(size_t)Bsz*Td*Od + 2*N1 + idx] = g_c[idx];    // cT
        return;
    }
    int idx2 = idx - 2*N1;
    if (idx2 >= Bsz*Od) return;
    int r = idx2 / Od, o = idx2 - r*Od;
    const float4* h4 = (const float4*)(g_h + BH + (size_t)r*Hd);
    const float4* w4 = (const float4*)(Wfc + (size_t)o*Hd);
    float acc = 0.f;
    #pragma unroll 16
    for (int j = 0; j < Hd/4; j++) {
        float4 a = h4[j], b = w4[j];
        acc += a.x*b.x + a.y*b.y + a.z*b.z + a.w*b.w;
    }
    out[(size_t)r*(Td*Od) + (Td-1)*Od + o] = acc + bfc[o];
}

extern "C" void kernel_launch(void* const* d_in, const int* in_sizes, int n_in,
                              void* d_out, int out_size) {
    const float* x   = (const float*)d_in[0];
    const float* h0  = (const float*)d_in[1];
    const float* c0  = (const float*)d_in[2];
    const float* Wih = (const float*)d_in[3];
    const float* Whh = (const float*)d_in[4];
    const float* bih = (const float*)d_in[5];
    const float* bhh = (const float*)d_in[6];
    const float* Wfc = (const float*)d_in[7];
    const float* bfc = (const float*)d_in[8];
    float* out = (float*)d_out;

    static int smem_set = 0;
    if (!smem_set) {
        cudaFuncSetAttribute(lstm_layer, cudaFuncAttributeMaxDynamicSharedMemorySize, DSMEM);
        smem_set = 1;
    }

    prep_weights<<<(Ld*G4*Kd + 255)/256, 256>>>(Wih, Whh, bih, bhh);
    prep_state<<<(Ld*BH + 255)/256, 256>>>(x, h0, c0);

    for (int t = 0; t < Td; t++) {
        lstm_layer<<<136, 256, DSMEM>>>(0, t, Wfc, bfc, out);   // + y_{t-1} in spare CTAs
        lstm_layer<<<128, 256, DSMEM>>>(1, t, Wfc, bfc, out);
    }
    finalize<<<(Ld*BH + Bsz*Od + 255)/256, 256>>>(Wfc, bfc, out);
}